// round 2
// baseline (speedup 1.0000x reference)
#include <cuda_runtime.h>
#include <cuda_bf16.h>
#include <cstdint>

// ---------------- problem constants ----------------
#define BATCH   2048
#define NATOM   96
#define NIN     128
#define NHID    64
#define SHIFTC  0.6931471805599453f

// ---------------- SMEM layout (byte offsets, all 16B aligned) ----------------
// A fragments: 6 m-tiles x 8 k-tiles x 32 lanes x 16B = 24576 per image
#define A_HI   0
#define A_LO   24576
// B fragments: 8 n-tiles x 8 k-tiles x 32 lanes x 8B = 16384 per image
#define B_HI   49152
#define B_LO   65536
#define OFF_B1 81920
#define OFF_W2 82176
#define OFF_SC 82432
#define OFF_RED 82448
#define SMEM_BYTES 82960

// ---------------- precomputed W1 hi/lo images (B-fragment layout) ----------------
__device__ __align__(16) unsigned char g_whi[16384];
__device__ __align__(16) unsigned char g_wlo[16384];

// W1 is [NIN=128][NHID=64] row-major.  B fragment layout for
// mma.m16n8k16.row.col: lane = g*4+tg holds b0 = W[n = nt*8+g][k = kt*16+2tg .. +1],
// b1 = same n, k+8.  Slot address: ((nt*8+kt)*32 + lane)*8 + breg*4 + odd*2.
__global__ void prep_w_kernel(const float* __restrict__ W1) {
    int idx = blockIdx.x * blockDim.x + threadIdx.x;
    if (idx >= NIN * NHID) return;
    int k = idx >> 6;          // 0..127
    int n = idx & 63;          // 0..63
    float w = W1[idx];
    __nv_bfloat16 hi = __float2bfloat16_rn(w);
    __nv_bfloat16 lo = __float2bfloat16_rn(w - __bfloat162float(hi));
    int nt = n >> 3, g = n & 7;
    int kt = k >> 4, kl = k & 15;
    int tg = (kl >> 1) & 3, br = kl >> 3, odd = kl & 1;
    uint32_t off = (uint32_t)(((nt * 8 + kt) * 32 + (g * 4 + tg)) * 8 + br * 4 + odd * 2);
    *reinterpret_cast<__nv_bfloat16*>(g_whi + off) = hi;
    *reinterpret_cast<__nv_bfloat16*>(g_wlo + off) = lo;
}

// ---------------- device helpers ----------------
__device__ __forceinline__ void mma_bf16(float* c, const uint32_t* a, const uint32_t* b) {
    asm volatile(
        "mma.sync.aligned.m16n8k16.row.col.f32.bf16.bf16.f32 "
        "{%0,%1,%2,%3}, {%4,%5,%6,%7}, {%8,%9}, {%0,%1,%2,%3};"
        : "+f"(c[0]), "+f"(c[1]), "+f"(c[2]), "+f"(c[3])
        : "r"(a[0]), "r"(a[1]), "r"(a[2]), "r"(a[3]), "r"(b[0]), "r"(b[1]));
}

__device__ __forceinline__ float ssp(float z) {
    // shifted softplus, numerically stable
    return fmaxf(z, 0.f) + __logf(1.f + __expf(-fabsf(z))) - SHIFTC;
}

// A-fragment slot for element (row, k-pair base k): lane slots XOR-swizzled by kt
// so the fill (fixed lane, kt varying across a warp) stays near conflict-free.
__device__ __forceinline__ uint32_t a_slot(int row, int k) {
    int t = row >> 4, g = row & 7, half = (row >> 3) & 1;
    int kt = k >> 4, kl = k & 15;
    int tg = (kl >> 1) & 3, khalf = kl >> 3;
    int reg = khalf * 2 + half;
    int lane = ((g * 4 + tg) ^ kt) & 31;
    return (uint32_t)(((t * 8 + kt) * 32 + lane) * 16 + reg * 4);
}

// ---------------- main fused kernel: one CTA per batch sample ----------------
__global__ __launch_bounds__(192)
void atomwise_kernel(const float* __restrict__ rep,
                     const int*   __restrict__ atomic_numbers,
                     const float* __restrict__ atom_mask,
                     const float* __restrict__ b1,
                     const float* __restrict__ W2,
                     const float* __restrict__ b2,
                     const float* __restrict__ atomref,
                     const float* __restrict__ mean,
                     const float* __restrict__ stddev,
                     float*       __restrict__ out) {
    extern __shared__ char bp[];
    const int tid  = threadIdx.x;
    const int w    = tid >> 5;
    const int lane = tid & 31;
    const int b    = blockIdx.x;

    // ---- stage W hi/lo fragment images: contiguous 16KB copies (L2-resident) ----
    {
        const uint4* shi = reinterpret_cast<const uint4*>(g_whi);
        const uint4* slo = reinterpret_cast<const uint4*>(g_wlo);
        uint4* dhi = reinterpret_cast<uint4*>(bp + B_HI);
        uint4* dlo = reinterpret_cast<uint4*>(bp + B_LO);
        for (int i = tid; i < 1024; i += 192) { dhi[i] = shi[i]; dlo[i] = slo[i]; }
    }

    // ---- load rep tile (96x128 fp32), hi/lo split into A-fragment layout ----
    {
        const float4* xsrc = reinterpret_cast<const float4*>(rep + (size_t)b * (NATOM * NIN));
        #pragma unroll
        for (int it = 0; it < 16; it++) {
            int e = tid * 4 + it * 768;           // element index, 4 at a time
            float4 v = xsrc[e >> 2];
            int row = e >> 7;
            int k   = e & 127;

            __nv_bfloat16 h0 = __float2bfloat16_rn(v.x);
            __nv_bfloat16 h1 = __float2bfloat16_rn(v.y);
            __nv_bfloat16 h2 = __float2bfloat16_rn(v.z);
            __nv_bfloat16 h3 = __float2bfloat16_rn(v.w);
            __nv_bfloat16 l0 = __float2bfloat16_rn(v.x - __bfloat162float(h0));
            __nv_bfloat16 l1 = __float2bfloat16_rn(v.y - __bfloat162float(h1));
            __nv_bfloat16 l2 = __float2bfloat16_rn(v.z - __bfloat162float(h2));
            __nv_bfloat16 l3 = __float2bfloat16_rn(v.w - __bfloat162float(h3));

            uint32_t o0 = a_slot(row, k);         // pair (k, k+1)
            uint32_t o1 = a_slot(row, k + 2);     // pair (k+2, k+3)
            *reinterpret_cast<__nv_bfloat162*>(bp + A_HI + o0) = __halves2bfloat162(h0, h1);
            *reinterpret_cast<__nv_bfloat162*>(bp + A_HI + o1) = __halves2bfloat162(h2, h3);
            *reinterpret_cast<__nv_bfloat162*>(bp + A_LO + o0) = __halves2bfloat162(l0, l1);
            *reinterpret_cast<__nv_bfloat162*>(bp + A_LO + o1) = __halves2bfloat162(l2, l3);
        }
    }

    // ---- stage small vectors ----
    if (tid < NHID) {
        reinterpret_cast<float*>(bp + OFF_B1)[tid] = b1[tid];
        reinterpret_cast<float*>(bp + OFF_W2)[tid] = W2[tid];
    }
    if (tid == 0) {
        float* sc = reinterpret_cast<float*>(bp + OFF_SC);
        sc[0] = b2[0]; sc[1] = mean[0]; sc[2] = stddev[0];
    }
    if (tid >= 96 && tid < 128) reinterpret_cast<float*>(bp + OFF_RED)[tid] = 0.f;
    __syncthreads();

    // ---- 3-chain hi/lo bf16 HMMA: D = Xhi*Whi + Xhi*Wlo + Xlo*Whi ----
    // warp w owns atom rows [16w, 16w+16); full N=64, K=128.
    float acc[8][4];
    #pragma unroll
    for (int nt = 0; nt < 8; nt++)
        #pragma unroll
        for (int r = 0; r < 4; r++) acc[nt][r] = 0.f;

    #pragma unroll
    for (int kt = 0; kt < 8; kt++) {
        int al = lane ^ kt;
        uint4 ahi = *reinterpret_cast<const uint4*>(bp + A_HI + ((w * 8 + kt) * 32 + al) * 16);
        uint4 alo = *reinterpret_cast<const uint4*>(bp + A_LO + ((w * 8 + kt) * 32 + al) * 16);
        #pragma unroll
        for (int nt = 0; nt < 8; nt++) {
            uint2 bhi = *reinterpret_cast<const uint2*>(bp + B_HI + ((nt * 8 + kt) * 32 + lane) * 8);
            uint2 blo = *reinterpret_cast<const uint2*>(bp + B_LO + ((nt * 8 + kt) * 32 + lane) * 8);
            mma_bf16(acc[nt], &ahi.x, &bhi.x);
            mma_bf16(acc[nt], &ahi.x, &blo.x);
            mma_bf16(acc[nt], &alo.x, &bhi.x);
        }
    }

    // ---- epilogue: bias + ssp + W2 dot, quad shuffle-reduce ----
    const float* sb1 = reinterpret_cast<const float*>(bp + OFF_B1);
    const float* sw2 = reinterpret_cast<const float*>(bp + OFF_W2);
    const float* sc  = reinterpret_cast<const float*>(bp + OFF_SC);

    float sumA = 0.f, sumB = 0.f;
    int tg2 = (lane & 3) * 2;
    #pragma unroll
    for (int nt = 0; nt < 8; nt++) {
        int c0 = nt * 8 + tg2;
        float b1a = sb1[c0], b1b = sb1[c0 + 1];
        float w2a = sw2[c0], w2b = sw2[c0 + 1];
        sumA = fmaf(ssp(acc[nt][0] + b1a), w2a, sumA);
        sumA = fmaf(ssp(acc[nt][1] + b1b), w2b, sumA);
        sumB = fmaf(ssp(acc[nt][2] + b1a), w2a, sumB);
        sumB = fmaf(ssp(acc[nt][3] + b1b), w2b, sumB);
    }
    sumA += __shfl_xor_sync(0xffffffffu, sumA, 1);
    sumA += __shfl_xor_sync(0xffffffffu, sumA, 2);
    sumB += __shfl_xor_sync(0xffffffffu, sumB, 1);
    sumB += __shfl_xor_sync(0xffffffffu, sumB, 2);

    float* red = reinterpret_cast<float*>(bp + OFF_RED);
    if ((lane & 3) == 0) {
        int g = lane >> 2;
        int rowA = w * 16 + g;
        int rowB = rowA + 8;
        float scB2 = sc[0], scMean = sc[1], scStd = sc[2];

        int gA = b * NATOM + rowA;
        float vA = (sumA + scB2) * scStd + scMean;
        vA += atomref[atomic_numbers[gA]];
        vA *= atom_mask[gA];
        red[rowA] = vA;

        int gB = b * NATOM + rowB;
        float vB = (sumB + scB2) * scStd + scMean;
        vB += atomref[atomic_numbers[gB]];
        vB *= atom_mask[gB];
        red[rowB] = vB;
    }
    __syncthreads();

    // ---- deterministic tree reduction over 128 slots (96 atoms + 32 zeros) ----
    #pragma unroll
    for (int s = 64; s > 0; s >>= 1) {
        if (tid < s) red[tid] += red[tid + s];
        __syncthreads();
    }
    if (tid == 0) out[b] = red[0];
}

// ---------------- host launch ----------------
extern "C" void kernel_launch(void* const* d_in, const int* in_sizes, int n_in,
                              void* d_out, int out_size) {
    const float* rep   = (const float*)d_in[0];
    const int*   zn    = (const int*)  d_in[1];
    const float* mask  = (const float*)d_in[2];
    const float* W1    = (const float*)d_in[3];
    const float* b1    = (const float*)d_in[4];
    const float* W2    = (const float*)d_in[5];
    const float* b2    = (const float*)d_in[6];
    const float* aref  = (const float*)d_in[7];
    const float* mean  = (const float*)d_in[8];
    const float* stdd  = (const float*)d_in[9];
    float* out = (float*)d_out;

    cudaFuncSetAttribute(atomwise_kernel, cudaFuncAttributeMaxDynamicSharedMemorySize, SMEM_BYTES);

    prep_w_kernel<<<32, 256>>>(W1);
    atomwise_kernel<<<BATCH, 192, SMEM_BYTES>>>(rep, zn, mask, b1, W2, b2, aref, mean, stdd, out);
}

// round 3
// speedup vs baseline: 1.0381x; 1.0381x over previous
#include <cuda_runtime.h>
#include <cuda_bf16.h>
#include <cstdint>

// ---------------- problem constants ----------------
#define BATCH   2048
#define NATOM   96
#define NIN     128
#define NHID    64
#define SHIFTC  0.6931471805599453f

// ---------------- precomputed W1 hi/lo images (B-fragment layout) ----------------
// Layout: uint2 index = (nt*8 + kt)*32 + lane  → per-warp 256B contiguous loads.
__device__ __align__(16) uint2 g_whi[2048];
__device__ __align__(16) uint2 g_wlo[2048];

// W1 is [NIN=128][NHID=64] row-major.  B fragment for mma.m16n8k16.row.col:
// lane = g*4+tg holds b0 = W[n=nt*8+g][k=kt*16+2tg+{0,1}], b1 = same n, k+8+{0,1}.
__global__ void prep_w_kernel(const float* __restrict__ W1) {
    int idx = blockIdx.x * blockDim.x + threadIdx.x;
    if (idx >= NIN * NHID) return;
    int k = idx >> 6;          // 0..127
    int n = idx & 63;          // 0..63
    float w = W1[idx];
    __nv_bfloat16 hi = __float2bfloat16_rn(w);
    __nv_bfloat16 lo = __float2bfloat16_rn(w - __bfloat162float(hi));
    int nt = n >> 3, g = n & 7;
    int kt = k >> 4, kl = k & 15;
    int tg = (kl >> 1) & 3, br = kl >> 3, odd = kl & 1;
    uint32_t off = (uint32_t)((((nt * 8 + kt) * 32 + (g * 4 + tg)) * 8) + br * 4 + odd * 2);
    *reinterpret_cast<__nv_bfloat16*>(reinterpret_cast<unsigned char*>(g_whi) + off) = hi;
    *reinterpret_cast<__nv_bfloat16*>(reinterpret_cast<unsigned char*>(g_wlo) + off) = lo;
}

// ---------------- device helpers ----------------
__device__ __forceinline__ void mma_bf16(float* c, const uint32_t* a, const uint32_t* b) {
    asm volatile(
        "mma.sync.aligned.m16n8k16.row.col.f32.bf16.bf16.f32 "
        "{%0,%1,%2,%3}, {%4,%5,%6,%7}, {%8,%9}, {%0,%1,%2,%3};"
        : "+f"(c[0]), "+f"(c[1]), "+f"(c[2]), "+f"(c[3])
        : "r"(a[0]), "r"(a[1]), "r"(a[2]), "r"(a[3]), "r"(b[0]), "r"(b[1]));
}

__device__ __forceinline__ float ssp(float z) {
    // shifted softplus, numerically stable
    return fmaxf(z, 0.f) + __logf(1.f + __expf(-fabsf(z))) - SHIFTC;
}

// hi/lo bf16 split of a float2 into packed bf16x2 registers
__device__ __forceinline__ void split2(float2 v, uint32_t& hi, uint32_t& lo) {
    __nv_bfloat162 h = __floats2bfloat162_rn(v.x, v.y);
    float rx = v.x - __low2float(h);
    float ry = v.y - __high2float(h);
    __nv_bfloat162 l = __floats2bfloat162_rn(rx, ry);
    hi = *reinterpret_cast<uint32_t*>(&h);
    lo = *reinterpret_cast<uint32_t*>(&l);
}

// ---------------- main fused kernel: one CTA per batch sample ----------------
__global__ void __launch_bounds__(192, 4)
atomwise_kernel(const float* __restrict__ rep,
                const int*   __restrict__ atomic_numbers,
                const float* __restrict__ atom_mask,
                const float* __restrict__ b1,
                const float* __restrict__ W2,
                const float* __restrict__ b2,
                const float* __restrict__ atomref,
                const float* __restrict__ mean,
                const float* __restrict__ stddev,
                float*       __restrict__ out) {
    __shared__ float red[8];

    const int tid  = threadIdx.x;
    const int w    = tid >> 5;          // warp 0..5, owns atom rows [16w, 16w+16)
    const int lane = tid & 31;
    const int b    = blockIdx.x;

    const int qr = lane >> 2;           // 0..7
    const int qc = lane & 3;            // 0..3
    const int r0 = w * 16 + qr;
    const int r1 = r0 + 8;

    const float* xbase = rep + (size_t)b * (NATOM * NIN);
    const float* xr0 = xbase + r0 * NIN + qc * 2;
    const float* xr1 = xbase + r1 * NIN + qc * 2;

    float acc[8][4];
    #pragma unroll
    for (int nt = 0; nt < 8; nt++)
        #pragma unroll
        for (int r = 0; r < 4; r++) acc[nt][r] = 0.f;

    // ---- 3-chain hi/lo bf16 HMMA: D = Xhi*Whi + Xhi*Wlo + Xlo*Whi ----
    #pragma unroll
    for (int kt = 0; kt < 8; kt++) {
        // A fragment: direct fp32 loads (warp pattern is 32B-sector aligned)
        float2 xa = *reinterpret_cast<const float2*>(xr0 + kt * 16);
        float2 xb = *reinterpret_cast<const float2*>(xr1 + kt * 16);
        float2 xc = *reinterpret_cast<const float2*>(xr0 + kt * 16 + 8);
        float2 xd = *reinterpret_cast<const float2*>(xr1 + kt * 16 + 8);

        uint32_t ahi[4], alo[4];
        split2(xa, ahi[0], alo[0]);
        split2(xb, ahi[1], alo[1]);
        split2(xc, ahi[2], alo[2]);
        split2(xd, ahi[3], alo[3]);

        #pragma unroll
        for (int nt = 0; nt < 8; nt++) {
            int bidx = (nt * 8 + kt) * 32 + lane;
            uint2 bh = __ldg(&g_whi[bidx]);
            uint2 bl = __ldg(&g_wlo[bidx]);
            mma_bf16(acc[nt], ahi, &bh.x);
            mma_bf16(acc[nt], ahi, &bl.x);
            mma_bf16(acc[nt], alo, &bh.x);
        }
    }

    // ---- epilogue: bias + ssp + W2 dot (cols of this thread), quad reduce ----
    float sumA = 0.f, sumB = 0.f;
    const int tg2 = qc * 2;
    #pragma unroll
    for (int nt = 0; nt < 8; nt++) {
        int c0 = nt * 8 + tg2;
        float2 b1v = *reinterpret_cast<const float2*>(b1 + c0);
        float2 w2v = *reinterpret_cast<const float2*>(W2 + c0);
        sumA = fmaf(ssp(acc[nt][0] + b1v.x), w2v.x, sumA);
        sumA = fmaf(ssp(acc[nt][1] + b1v.y), w2v.y, sumA);
        sumB = fmaf(ssp(acc[nt][2] + b1v.x), w2v.x, sumB);
        sumB = fmaf(ssp(acc[nt][3] + b1v.y), w2v.y, sumB);
    }
    // reduce over the 4 lanes of each quad (cols)
    sumA += __shfl_xor_sync(0xffffffffu, sumA, 1);
    sumA += __shfl_xor_sync(0xffffffffu, sumA, 2);
    sumB += __shfl_xor_sync(0xffffffffu, sumB, 1);
    sumB += __shfl_xor_sync(0xffffffffu, sumB, 2);

    // per-row finish on quad leaders, then warp-sum (deterministic)
    float contrib = 0.f;
    if (qc == 0) {
        float scB2 = b2[0], scMean = mean[0], scStd = stddev[0];

        int gA = b * NATOM + r0;
        float vA = (sumA + scB2) * scStd + scMean;
        vA += atomref[atomic_numbers[gA]];
        vA *= atom_mask[gA];

        int gB = b * NATOM + r1;
        float vB = (sumB + scB2) * scStd + scMean;
        vB += atomref[atomic_numbers[gB]];
        vB *= atom_mask[gB];

        contrib = vA + vB;
    }
    // nonzero only at lanes ≡ 0 (mod 4): stages 4, 8, 16 suffice
    contrib += __shfl_xor_sync(0xffffffffu, contrib, 4);
    contrib += __shfl_xor_sync(0xffffffffu, contrib, 8);
    contrib += __shfl_xor_sync(0xffffffffu, contrib, 16);

    if (lane == 0) red[w] = contrib;
    __syncthreads();
    if (tid == 0) {
        float s = red[0];
        #pragma unroll
        for (int i = 1; i < 6; i++) s += red[i];
        out[b] = s;
    }
}

// ---------------- host launch ----------------
extern "C" void kernel_launch(void* const* d_in, const int* in_sizes, int n_in,
                              void* d_out, int out_size) {
    const float* rep   = (const float*)d_in[0];
    const int*   zn    = (const int*)  d_in[1];
    const float* mask  = (const float*)d_in[2];
    const float* W1    = (const float*)d_in[3];
    const float* b1    = (const float*)d_in[4];
    const float* W2    = (const float*)d_in[5];
    const float* b2    = (const float*)d_in[6];
    const float* aref  = (const float*)d_in[7];
    const float* mean  = (const float*)d_in[8];
    const float* stdd  = (const float*)d_in[9];
    float* out = (float*)d_out;

    prep_w_kernel<<<32, 256>>>(W1);
    atomwise_kernel<<<BATCH, 192>>>(rep, zn, mask, b1, W2, b2, aref, mean, stdd, out);
}

// round 4
// speedup vs baseline: 1.2835x; 1.2364x over previous
#include <cuda_runtime.h>
#include <cuda_bf16.h>
#include <cstdint>

// ---------------- problem constants ----------------
#define BATCH   2048
#define NATOM   96
#define NIN     128
#define NHID    64
#define SHIFTC  0.6931471805599453f

// ---------------- precomputed W1 hi/lo packed image (B-fragment layout) ----------------
// uint4 index = (nt*8 + kt)*32 + lane ; .xy = hi pair (b0,b1), .zw = lo pair (b0,b1)
__device__ __align__(16) uint4 g_wpk[2048];   // 32 KB, L2-resident

// W1 is [NIN=128][NHID=64] row-major.  B fragment for mma.m16n8k16.row.col:
// lane = g*4+tg holds b0 = W[n=nt*8+g][k=kt*16+2tg+{0,1}], b1 = same n, k+8+{0,1}.
__global__ void prep_w_kernel(const float* __restrict__ W1) {
    int idx = blockIdx.x * blockDim.x + threadIdx.x;
    if (idx >= NIN * NHID) return;
    int k = idx >> 6;          // 0..127
    int n = idx & 63;          // 0..63
    float w = W1[idx];
    __nv_bfloat16 hi = __float2bfloat16_rn(w);
    __nv_bfloat16 lo = __float2bfloat16_rn(w - __bfloat162float(hi));
    int nt = n >> 3, g = n & 7;
    int kt = k >> 4, kl = k & 15;
    int tg = (kl >> 1) & 3, br = kl >> 3, odd = kl & 1;
    uint32_t base = (uint32_t)(((nt * 8 + kt) * 32 + (g * 4 + tg)) * 16);
    unsigned char* p = reinterpret_cast<unsigned char*>(g_wpk);
    *reinterpret_cast<__nv_bfloat16*>(p + base + br * 4 + odd * 2)     = hi;
    *reinterpret_cast<__nv_bfloat16*>(p + base + 8 + br * 4 + odd * 2) = lo;
}

// ---------------- device helpers ----------------
__device__ __forceinline__ void mma_bf16(float* c, const uint32_t* a, const uint32_t* b) {
    asm volatile(
        "mma.sync.aligned.m16n8k16.row.col.f32.bf16.bf16.f32 "
        "{%0,%1,%2,%3}, {%4,%5,%6,%7}, {%8,%9}, {%0,%1,%2,%3};"
        : "+f"(c[0]), "+f"(c[1]), "+f"(c[2]), "+f"(c[3])
        : "r"(a[0]), "r"(a[1]), "r"(a[2]), "r"(a[3]), "r"(b[0]), "r"(b[1]));
}

__device__ __forceinline__ float ssp(float z) {
    // shifted softplus, numerically stable
    return fmaxf(z, 0.f) + __logf(1.f + __expf(-fabsf(z))) - SHIFTC;
}

// hi/lo bf16 split of a float2 into packed bf16x2 registers
__device__ __forceinline__ void split2(float2 v, uint32_t& hi, uint32_t& lo) {
    __nv_bfloat162 h = __floats2bfloat162_rn(v.x, v.y);
    float rx = v.x - __low2float(h);
    float ry = v.y - __high2float(h);
    __nv_bfloat162 l = __floats2bfloat162_rn(rx, ry);
    hi = *reinterpret_cast<uint32_t*>(&h);
    lo = *reinterpret_cast<uint32_t*>(&l);
}

// ---------------- main fused kernel: one CTA (3 warps) per batch sample ----------------
// Warp w owns atom rows [32w, 32w+32) as TWO m16 tiles -> each B load feeds 6 MMAs,
// and two independent accumulation chains per nt double tensor-pipe ILP.
__global__ void __launch_bounds__(96, 4)
atomwise_kernel(const float* __restrict__ rep,
                const int*   __restrict__ atomic_numbers,
                const float* __restrict__ atom_mask,
                const float* __restrict__ b1,
                const float* __restrict__ W2,
                const float* __restrict__ b2,
                const float* __restrict__ atomref,
                const float* __restrict__ mean,
                const float* __restrict__ stddev,
                float*       __restrict__ out) {
    __shared__ float red[4];

    const int tid  = threadIdx.x;
    const int w    = tid >> 5;          // warp 0..2
    const int lane = tid & 31;
    const int b    = blockIdx.x;

    const int qr = lane >> 2;           // 0..7 (row group)
    const int qc = lane & 3;            // 0..3 (col group)
    const int r0 = w * 32 + qr;         // rows r0, r0+8 (m-tile 0); r0+16, r0+24 (m-tile 1)

    const float* xb = rep + (size_t)b * (NATOM * NIN);
    const float* p0 = xb + (r0     ) * NIN + qc * 2;
    const float* p1 = xb + (r0 +  8) * NIN + qc * 2;
    const float* p2 = xb + (r0 + 16) * NIN + qc * 2;
    const float* p3 = xb + (r0 + 24) * NIN + qc * 2;

    float acc[2][8][4];
    #pragma unroll
    for (int m = 0; m < 2; m++)
        #pragma unroll
        for (int nt = 0; nt < 8; nt++)
            #pragma unroll
            for (int r = 0; r < 4; r++) acc[m][nt][r] = 0.f;

    // ---- 3-chain hi/lo bf16 HMMA: D = Xhi*Whi + Xhi*Wlo + Xlo*Whi ----
    #pragma unroll
    for (int kt = 0; kt < 8; kt++) {
        // A fragments for both m-tiles: direct fp32 loads (32B-sector aligned per quad)
        float2 x0 = __ldg(reinterpret_cast<const float2*>(p0 + kt * 16));
        float2 x1 = __ldg(reinterpret_cast<const float2*>(p1 + kt * 16));
        float2 x2 = __ldg(reinterpret_cast<const float2*>(p0 + kt * 16 + 8));
        float2 x3 = __ldg(reinterpret_cast<const float2*>(p1 + kt * 16 + 8));
        float2 y0 = __ldg(reinterpret_cast<const float2*>(p2 + kt * 16));
        float2 y1 = __ldg(reinterpret_cast<const float2*>(p3 + kt * 16));
        float2 y2 = __ldg(reinterpret_cast<const float2*>(p2 + kt * 16 + 8));
        float2 y3 = __ldg(reinterpret_cast<const float2*>(p3 + kt * 16 + 8));

        uint32_t ahi0[4], alo0[4], ahi1[4], alo1[4];
        split2(x0, ahi0[0], alo0[0]);
        split2(x1, ahi0[1], alo0[1]);
        split2(x2, ahi0[2], alo0[2]);
        split2(x3, ahi0[3], alo0[3]);
        split2(y0, ahi1[0], alo1[0]);
        split2(y1, ahi1[1], alo1[1]);
        split2(y2, ahi1[2], alo1[2]);
        split2(y3, ahi1[3], alo1[3]);

        #pragma unroll
        for (int nt = 0; nt < 8; nt++) {
            uint4 bb = __ldg(&g_wpk[(nt * 8 + kt) * 32 + lane]);
            // two independent chains (m-tile 0 / m-tile 1) per nt
            mma_bf16(acc[0][nt], ahi0, &bb.x);   // hi*hi
            mma_bf16(acc[1][nt], ahi1, &bb.x);
            mma_bf16(acc[0][nt], ahi0, &bb.z);   // hi*lo
            mma_bf16(acc[1][nt], ahi1, &bb.z);
            mma_bf16(acc[0][nt], alo0, &bb.x);   // lo*hi
            mma_bf16(acc[1][nt], alo1, &bb.x);
        }
    }

    // ---- epilogue: bias + ssp + W2 dot, quad shuffle-reduce ----
    float sum0 = 0.f, sum1 = 0.f, sum2 = 0.f, sum3 = 0.f;  // rows r0, r0+8, r0+16, r0+24
    const int tg2 = qc * 2;
    #pragma unroll
    for (int nt = 0; nt < 8; nt++) {
        int c0 = nt * 8 + tg2;
        float2 b1v = __ldg(reinterpret_cast<const float2*>(b1 + c0));
        float2 w2v = __ldg(reinterpret_cast<const float2*>(W2 + c0));
        sum0 = fmaf(ssp(acc[0][nt][0] + b1v.x), w2v.x, sum0);
        sum0 = fmaf(ssp(acc[0][nt][1] + b1v.y), w2v.y, sum0);
        sum1 = fmaf(ssp(acc[0][nt][2] + b1v.x), w2v.x, sum1);
        sum1 = fmaf(ssp(acc[0][nt][3] + b1v.y), w2v.y, sum1);
        sum2 = fmaf(ssp(acc[1][nt][0] + b1v.x), w2v.x, sum2);
        sum2 = fmaf(ssp(acc[1][nt][1] + b1v.y), w2v.y, sum2);
        sum3 = fmaf(ssp(acc[1][nt][2] + b1v.x), w2v.x, sum3);
        sum3 = fmaf(ssp(acc[1][nt][3] + b1v.y), w2v.y, sum3);
    }
    // reduce over the 4 lanes of each quad (cols)
    sum0 += __shfl_xor_sync(0xffffffffu, sum0, 1);
    sum0 += __shfl_xor_sync(0xffffffffu, sum0, 2);
    sum1 += __shfl_xor_sync(0xffffffffu, sum1, 1);
    sum1 += __shfl_xor_sync(0xffffffffu, sum1, 2);
    sum2 += __shfl_xor_sync(0xffffffffu, sum2, 1);
    sum2 += __shfl_xor_sync(0xffffffffu, sum2, 2);
    sum3 += __shfl_xor_sync(0xffffffffu, sum3, 1);
    sum3 += __shfl_xor_sync(0xffffffffu, sum3, 2);

    // per-row finish on quad leaders, then warp-sum (deterministic)
    float contrib = 0.f;
    if (qc == 0) {
        float scB2 = b2[0], scMean = mean[0], scStd = stddev[0];
        float s[4] = {sum0, sum1, sum2, sum3};
        float tot = 0.f;
        #pragma unroll
        for (int m = 0; m < 4; m++) {
            int row = r0 + m * 8;
            int g = b * NATOM + row;
            float v = (s[m] + scB2) * scStd + scMean;
            v += atomref[atomic_numbers[g]];
            v *= atom_mask[g];
            tot += v;
        }
        contrib = tot;
    }
    // nonzero only at lanes ≡ 0 (mod 4): stages 4, 8, 16 suffice
    contrib += __shfl_xor_sync(0xffffffffu, contrib, 4);
    contrib += __shfl_xor_sync(0xffffffffu, contrib, 8);
    contrib += __shfl_xor_sync(0xffffffffu, contrib, 16);

    if (lane == 0) red[w] = contrib;
    __syncthreads();
    if (tid == 0) out[b] = red[0] + red[1] + red[2];
}

// ---------------- host launch ----------------
extern "C" void kernel_launch(void* const* d_in, const int* in_sizes, int n_in,
                              void* d_out, int out_size) {
    const float* rep   = (const float*)d_in[0];
    const int*   zn    = (const int*)  d_in[1];
    const float* mask  = (const float*)d_in[2];
    const float* W1    = (const float*)d_in[3];
    const float* b1    = (const float*)d_in[4];
    const float* W2    = (const float*)d_in[5];
    const float* b2    = (const float*)d_in[6];
    const float* aref  = (const float*)d_in[7];
    const float* mean  = (const float*)d_in[8];
    const float* stdd  = (const float*)d_in[9];
    float* out = (float*)d_out;

    prep_w_kernel<<<32, 256>>>(W1);
    atomwise_kernel<<<BATCH, 96>>>(rep, zn, mask, b1, W2, b2, aref, mean, stdd, out);
}

// round 5
// speedup vs baseline: 1.2949x; 1.0089x over previous
#include <cuda_runtime.h>
#include <cuda_bf16.h>
#include <cstdint>

// ---------------- problem constants ----------------
#define BATCH   2048
#define NATOM   96
#define NIN     128
#define NHID    64
#define SHIFTC  0.6931471805599453f

// ---------------- precomputed W1 hi/lo packed image (B-fragment layout) ----------------
// uint4 index = (nt*8 + kt)*32 + lane ; .xy = hi pair (b0,b1), .zw = lo pair (b0,b1)
__device__ __align__(16) uint4 g_wpk[2048];   // 32 KB, L2/L1-resident

// W1 is [NIN=128][NHID=64] row-major.  B fragment for mma.m16n8k16.row.col:
// lane = g*4+tg holds b0 = W[n=nt*8+g][k=kt*16+2tg+{0,1}], b1 = same n, k+8+{0,1}.
__global__ void prep_w_kernel(const float* __restrict__ W1) {
    int idx = blockIdx.x * blockDim.x + threadIdx.x;
    if (idx >= NIN * NHID) return;
    int k = idx >> 6;          // 0..127
    int n = idx & 63;          // 0..63
    float w = W1[idx];
    __nv_bfloat16 hi = __float2bfloat16_rn(w);
    __nv_bfloat16 lo = __float2bfloat16_rn(w - __bfloat162float(hi));
    int nt = n >> 3, g = n & 7;
    int kt = k >> 4, kl = k & 15;
    int tg = (kl >> 1) & 3, br = kl >> 3, odd = kl & 1;
    uint32_t base = (uint32_t)(((nt * 8 + kt) * 32 + (g * 4 + tg)) * 16);
    unsigned char* p = reinterpret_cast<unsigned char*>(g_wpk);
    *reinterpret_cast<__nv_bfloat16*>(p + base + br * 4 + odd * 2)     = hi;
    *reinterpret_cast<__nv_bfloat16*>(p + base + 8 + br * 4 + odd * 2) = lo;
}

// ---------------- device helpers ----------------
__device__ __forceinline__ void mma_bf16(float* c, const uint32_t* a, const uint32_t* b) {
    asm volatile(
        "mma.sync.aligned.m16n8k16.row.col.f32.bf16.bf16.f32 "
        "{%0,%1,%2,%3}, {%4,%5,%6,%7}, {%8,%9}, {%0,%1,%2,%3};"
        : "+f"(c[0]), "+f"(c[1]), "+f"(c[2]), "+f"(c[3])
        : "r"(a[0]), "r"(a[1]), "r"(a[2]), "r"(a[3]), "r"(b[0]), "r"(b[1]));
}

__device__ __forceinline__ float ssp(float z) {
    // shifted softplus, numerically stable
    return fmaxf(z, 0.f) + __logf(1.f + __expf(-fabsf(z))) - SHIFTC;
}

// hi/lo bf16 split of a float2 into packed bf16x2 registers
__device__ __forceinline__ void split2(float2 v, uint32_t& hi, uint32_t& lo) {
    __nv_bfloat162 h = __floats2bfloat162_rn(v.x, v.y);
    float rx = v.x - __low2float(h);
    float ry = v.y - __high2float(h);
    __nv_bfloat162 l = __floats2bfloat162_rn(rx, ry);
    hi = *reinterpret_cast<uint32_t*>(&h);
    lo = *reinterpret_cast<uint32_t*>(&l);
}

// ---------------- main fused kernel: one CTA (3 warps) per batch sample ----------------
// Warp w owns atom rows [32w, 32w+32) as TWO m16 tiles.  Per kt, MMAs run in THREE
// PASSES over nt (hi*hi, hi*lo, lo*hi): every MMA in a pass hits a distinct
// accumulator, so the tensor pipe sees an independent 16-MMA issue stream instead
// of 3-deep dependent chains.
__global__ void __launch_bounds__(96, 4)
atomwise_kernel(const float* __restrict__ rep,
                const int*   __restrict__ atomic_numbers,
                const float* __restrict__ atom_mask,
                const float* __restrict__ b1,
                const float* __restrict__ W2,
                const float* __restrict__ b2,
                const float* __restrict__ atomref,
                const float* __restrict__ mean,
                const float* __restrict__ stddev,
                float*       __restrict__ out) {
    __shared__ float red[4];

    const int tid  = threadIdx.x;
    const int w    = tid >> 5;          // warp 0..2
    const int lane = tid & 31;
    const int b    = blockIdx.x;

    const int qr = lane >> 2;           // 0..7 (row group)
    const int qc = lane & 3;            // 0..3 (col group)
    const int r0 = w * 32 + qr;         // rows r0, r0+8 (m-tile 0); r0+16, r0+24 (m-tile 1)

    const float* xb = rep + (size_t)b * (NATOM * NIN);
    const float* p0 = xb + (r0     ) * NIN + qc * 2;
    const float* p1 = xb + (r0 +  8) * NIN + qc * 2;
    const float* p2 = xb + (r0 + 16) * NIN + qc * 2;
    const float* p3 = xb + (r0 + 24) * NIN + qc * 2;

    float acc[2][8][4];
    #pragma unroll
    for (int m = 0; m < 2; m++)
        #pragma unroll
        for (int nt = 0; nt < 8; nt++)
            #pragma unroll
            for (int r = 0; r < 4; r++) acc[m][nt][r] = 0.f;

    // ---- 3-chain hi/lo bf16 HMMA: D = Xhi*Whi + Xhi*Wlo + Xlo*Whi ----
    #pragma unroll
    for (int kt = 0; kt < 8; kt++) {
        // batched B fragment loads for this kt (independent, high MLP)
        uint4 bb[8];
        #pragma unroll
        for (int nt = 0; nt < 8; nt++)
            bb[nt] = __ldg(&g_wpk[(nt * 8 + kt) * 32 + lane]);

        // A fragments for both m-tiles: direct fp32 loads (32B-sector aligned per quad)
        float2 x0 = __ldg(reinterpret_cast<const float2*>(p0 + kt * 16));
        float2 x1 = __ldg(reinterpret_cast<const float2*>(p1 + kt * 16));
        float2 x2 = __ldg(reinterpret_cast<const float2*>(p0 + kt * 16 + 8));
        float2 x3 = __ldg(reinterpret_cast<const float2*>(p1 + kt * 16 + 8));
        float2 y0 = __ldg(reinterpret_cast<const float2*>(p2 + kt * 16));
        float2 y1 = __ldg(reinterpret_cast<const float2*>(p3 + kt * 16));
        float2 y2 = __ldg(reinterpret_cast<const float2*>(p2 + kt * 16 + 8));
        float2 y3 = __ldg(reinterpret_cast<const float2*>(p3 + kt * 16 + 8));

        uint32_t ahi0[4], alo0[4], ahi1[4], alo1[4];
        split2(x0, ahi0[0], alo0[0]);
        split2(x1, ahi0[1], alo0[1]);
        split2(x2, ahi0[2], alo0[2]);
        split2(x3, ahi0[3], alo0[3]);
        split2(y0, ahi1[0], alo1[0]);
        split2(y1, ahi1[1], alo1[1]);
        split2(y2, ahi1[2], alo1[2]);
        split2(y3, ahi1[3], alo1[3]);

        // PASS 1: hi * hi  (16 independent MMAs)
        #pragma unroll
        for (int nt = 0; nt < 8; nt++) {
            mma_bf16(acc[0][nt], ahi0, &bb[nt].x);
            mma_bf16(acc[1][nt], ahi1, &bb[nt].x);
        }
        // PASS 2: hi * lo
        #pragma unroll
        for (int nt = 0; nt < 8; nt++) {
            mma_bf16(acc[0][nt], ahi0, &bb[nt].z);
            mma_bf16(acc[1][nt], ahi1, &bb[nt].z);
        }
        // PASS 3: lo * hi
        #pragma unroll
        for (int nt = 0; nt < 8; nt++) {
            mma_bf16(acc[0][nt], alo0, &bb[nt].x);
            mma_bf16(acc[1][nt], alo1, &bb[nt].x);
        }
    }

    // ---- epilogue: bias + ssp + W2 dot, quad shuffle-reduce ----
    float sum0 = 0.f, sum1 = 0.f, sum2 = 0.f, sum3 = 0.f;  // rows r0, r0+8, r0+16, r0+24
    const int tg2 = qc * 2;
    #pragma unroll
    for (int nt = 0; nt < 8; nt++) {
        int c0 = nt * 8 + tg2;
        float2 b1v = __ldg(reinterpret_cast<const float2*>(b1 + c0));
        float2 w2v = __ldg(reinterpret_cast<const float2*>(W2 + c0));
        sum0 = fmaf(ssp(acc[0][nt][0] + b1v.x), w2v.x, sum0);
        sum0 = fmaf(ssp(acc[0][nt][1] + b1v.y), w2v.y, sum0);
        sum1 = fmaf(ssp(acc[0][nt][2] + b1v.x), w2v.x, sum1);
        sum1 = fmaf(ssp(acc[0][nt][3] + b1v.y), w2v.y, sum1);
        sum2 = fmaf(ssp(acc[1][nt][0] + b1v.x), w2v.x, sum2);
        sum2 = fmaf(ssp(acc[1][nt][1] + b1v.y), w2v.y, sum2);
        sum3 = fmaf(ssp(acc[1][nt][2] + b1v.x), w2v.x, sum3);
        sum3 = fmaf(ssp(acc[1][nt][3] + b1v.y), w2v.y, sum3);
    }
    // reduce over the 4 lanes of each quad (cols)
    sum0 += __shfl_xor_sync(0xffffffffu, sum0, 1);
    sum0 += __shfl_xor_sync(0xffffffffu, sum0, 2);
    sum1 += __shfl_xor_sync(0xffffffffu, sum1, 1);
    sum1 += __shfl_xor_sync(0xffffffffu, sum1, 2);
    sum2 += __shfl_xor_sync(0xffffffffu, sum2, 1);
    sum2 += __shfl_xor_sync(0xffffffffu, sum2, 2);
    sum3 += __shfl_xor_sync(0xffffffffu, sum3, 1);
    sum3 += __shfl_xor_sync(0xffffffffu, sum3, 2);

    // per-row finish on quad leaders, then warp-sum (deterministic)
    float contrib = 0.f;
    if (qc == 0) {
        float scB2 = b2[0], scMean = mean[0], scStd = stddev[0];
        float s[4] = {sum0, sum1, sum2, sum3};
        float tot = 0.f;
        #pragma unroll
        for (int m = 0; m < 4; m++) {
            int row = r0 + m * 8;
            int g = b * NATOM + row;
            float v = (s[m] + scB2) * scStd + scMean;
            v += atomref[atomic_numbers[g]];
            v *= atom_mask[g];
            tot += v;
        }
        contrib = tot;
    }
    // nonzero only at lanes ≡ 0 (mod 4): stages 4, 8, 16 suffice
    contrib += __shfl_xor_sync(0xffffffffu, contrib, 4);
    contrib += __shfl_xor_sync(0xffffffffu, contrib, 8);
    contrib += __shfl_xor_sync(0xffffffffu, contrib, 16);

    if (lane == 0) red[w] = contrib;
    __syncthreads();
    if (tid == 0) out[b] = red[0] + red[1] + red[2];
}

// ---------------- host launch ----------------
extern "C" void kernel_launch(void* const* d_in, const int* in_sizes, int n_in,
                              void* d_out, int out_size) {
    const float* rep   = (const float*)d_in[0];
    const int*   zn    = (const int*)  d_in[1];
    const float* mask  = (const float*)d_in[2];
    const float* W1    = (const float*)d_in[3];
    const float* b1    = (const float*)d_in[4];
    const float* W2    = (const float*)d_in[5];
    const float* b2    = (const float*)d_in[6];
    const float* aref  = (const float*)d_in[7];
    const float* mean  = (const float*)d_in[8];
    const float* stdd  = (const float*)d_in[9];
    float* out = (float*)d_out;

    prep_w_kernel<<<32, 256>>>(W1);
    atomwise_kernel<<<BATCH, 96>>>(rep, zn, mask, b1, W2, b2, aref, mean, stdd, out);
}